// round 14
// baseline (speedup 1.0000x reference)
#include <cuda_runtime.h>
#include <cuda_bf16.h>

#define BATCH 1024

// PDL controls: every kernel signals dependents may begin their prologue;
// dependents block on GDC_WAIT before touching the predecessor's output.
#define GDC_LAUNCH asm volatile("griddepcontrol.launch_dependents;" ::: "memory")
#define GDC_WAIT   asm volatile("griddepcontrol.wait;" ::: "memory")

// ---------------------------------------------------------------------------
__device__ float g_xt[3 * 32 * 32 * BATCH];   // (3,32,32,B)
__device__ float g_h1[6 * 14 * 14 * BATCH];   // conv1+relu+pool
__device__ float g_h2[16 * 5 * 5 * BATCH];    // conv2+relu+pool
__device__ float g_p3[20 * 120 * BATCH];      // conv3 K-split partials (20 way)
__device__ float g_h3[120 * BATCH];           // conv3+relu
__device__ float g_p4[5 * 84 * BATCH];        // fc2 K-split partials (5 way)
__device__ float g_h4[84 * BATCH];            // fc2+relu

using u64 = unsigned long long;
struct __align__(16) U2 { u64 lo, hi; };

__device__ __forceinline__ u64 ffma2(u64 a, u64 b, u64 c) {
    u64 d;
    asm("fma.rn.f32x2 %0, %1, %2, %3;" : "=l"(d) : "l"(a), "l"(b), "l"(c));
    return d;
}
__device__ __forceinline__ u64 pk2(float x, float y) {
    u64 r; asm("mov.b64 %0, {%1, %2};" : "=l"(r) : "f"(x), "f"(y)); return r;
}
__device__ __forceinline__ float2 upk(u64 v) {
    float2 r; asm("mov.b64 {%0, %1}, %2;" : "=f"(r.x), "=f"(r.y) : "l"(v)); return r;
}

// ---------------------------------------------------------------------------
// Transpose x (B,3072) -> (3072,B)
// ---------------------------------------------------------------------------
__global__ __launch_bounds__(256) void k_transpose(const float* __restrict__ x) {
    GDC_LAUNCH;
    __shared__ float t[32][133];
    int p0 = blockIdx.x * 128;
    int b0 = blockIdx.y * 32;
    int tx = threadIdx.x & 31, ty = threadIdx.x >> 5;
#pragma unroll
    for (int rr = 0; rr < 4; rr++) {
        int row = ty + 8 * rr;
        float4 v = *(const float4*)&x[(b0 + row) * 3072 + p0 + 4 * tx];
        t[row][4 * tx + 0] = v.x; t[row][4 * tx + 1] = v.y;
        t[row][4 * tx + 2] = v.z; t[row][4 * tx + 3] = v.w;
    }
    __syncthreads();
#pragma unroll
    for (int q = 0; q < 4; q++) {
        int idx = q * 256 + threadIdx.x;
        int pp = idx >> 3;
        int bg = idx & 7;
        float4 v = make_float4(t[4 * bg + 0][pp], t[4 * bg + 1][pp],
                               t[4 * bg + 2][pp], t[4 * bg + 3][pp]);
        *(float4*)&g_xt[(p0 + pp) * BATCH + b0 + 4 * bg] = v;
    }
}

// ---------------------------------------------------------------------------
// conv1: untied 5x5, 3->6, +relu+pool. o-tile 3, thread = 4 images.
// Grid (196 loc, 2 og) = 392 CTAs x 256 thr.
// ---------------------------------------------------------------------------
__global__ __launch_bounds__(256) void k_conv1(const float* __restrict__ w1,
                                               const float* __restrict__ b1) {
    GDC_LAUNCH;
    __shared__ __align__(16) u64 ws[3][4][5][3][6];   // [c][pos][ky][o][kx]
    __shared__ float bs[3][4];
    int loc = blockIdx.x;
    int py = loc / 14, px = loc % 14;
    int og = blockIdx.y * 3;
    int tid = threadIdx.x;
    int b = tid * 4;

    for (int i = tid; i < 900; i += 256) {
        int o = i / 300, r = i % 300;
        int pos = r / 75, r2 = r % 75;
        int c = r2 / 25, k = r2 % 25;
        int ky = k / 5, kx = k % 5;
        int ho = 2 * py + (pos >> 1), wo = 2 * px + (pos & 1);
        float w = w1[((((og + o) * 3 + c) * 28 + ho) * 28 + wo) * 25 + k];
        ws[c][pos][ky][o][kx] = pk2(w, w);
    }
    if (tid < 12) {
        int o = tid / 4, pos = tid % 4;
        int ho = 2 * py + (pos >> 1), wo = 2 * px + (pos & 1);
        bs[o][pos] = b1[((og + o) * 28 + ho) * 28 + wo];
    }
    __syncthreads();
    GDC_WAIT;   // g_xt ready past here

    u64 acc[3][4][2];
#pragma unroll
    for (int i = 0; i < 24; i++) (&acc[0][0][0])[i] = 0ull;

    const float* base0 = &g_xt[((2 * py) * 32 + 2 * px) * BATCH + b];
    U2 abuf[2][6];
#pragma unroll
    for (int ix = 0; ix < 6; ix++) abuf[0][ix] = *(const U2*)&base0[ix * BATCH];

#pragma unroll 1
    for (int c = 0; c < 3; c++) {
        const float* base = base0 + c * (1024 * BATCH);
#pragma unroll
        for (int iy = 0; iy < 6; iy++) {
            int cur = iy & 1, nxt = cur ^ 1;
            const float* np = (iy < 5) ? base + (iy + 1) * (32 * BATCH)
                                       : base + ((c < 2) ? 1024 * BATCH : 0);
#pragma unroll
            for (int ix = 0; ix < 6; ix++) abuf[nxt][ix] = *(const U2*)&np[ix * BATCH];
#pragma unroll
            for (int dy = 0; dy < 2; dy++) {
                int ky = iy - dy;
                if (ky < 0 || ky > 4) continue;
#pragma unroll
                for (int o = 0; o < 3; o++)
#pragma unroll
                    for (int dx = 0; dx < 2; dx++) {
                        int pos = dy * 2 + dx;
                        U2 w01 = *(const U2*)&ws[c][pos][ky][o][0];
                        U2 w23 = *(const U2*)&ws[c][pos][ky][o][2];
                        u64 w4 = ws[c][pos][ky][o][4];
                        u64* ap = &acc[o][pos][0];
                        ap[0] = ffma2(w01.lo, abuf[cur][0 + dx].lo, ap[0]);
                        ap[1] = ffma2(w01.lo, abuf[cur][0 + dx].hi, ap[1]);
                        ap[0] = ffma2(w01.hi, abuf[cur][1 + dx].lo, ap[0]);
                        ap[1] = ffma2(w01.hi, abuf[cur][1 + dx].hi, ap[1]);
                        ap[0] = ffma2(w23.lo, abuf[cur][2 + dx].lo, ap[0]);
                        ap[1] = ffma2(w23.lo, abuf[cur][2 + dx].hi, ap[1]);
                        ap[0] = ffma2(w23.hi, abuf[cur][3 + dx].lo, ap[0]);
                        ap[1] = ffma2(w23.hi, abuf[cur][3 + dx].hi, ap[1]);
                        ap[0] = ffma2(w4, abuf[cur][4 + dx].lo, ap[0]);
                        ap[1] = ffma2(w4, abuf[cur][4 + dx].hi, ap[1]);
                    }
            }
        }
    }
#pragma unroll
    for (int o = 0; o < 3; o++) {
        float2 a0 = upk(acc[o][0][0]), a1 = upk(acc[o][1][0]);
        float2 a2 = upk(acc[o][2][0]), a3 = upk(acc[o][3][0]);
        float2 c0 = upk(acc[o][0][1]), c1 = upk(acc[o][1][1]);
        float2 c2 = upk(acc[o][2][1]), c3 = upk(acc[o][3][1]);
        float b0v = bs[o][0], b1v = bs[o][1], b2v = bs[o][2], b3v = bs[o][3];
        float4 r;
        r.x = fmaxf(fmaxf(fmaxf(a0.x + b0v, a1.x + b1v), fmaxf(a2.x + b2v, a3.x + b3v)), 0.0f);
        r.y = fmaxf(fmaxf(fmaxf(a0.y + b0v, a1.y + b1v), fmaxf(a2.y + b2v, a3.y + b3v)), 0.0f);
        r.z = fmaxf(fmaxf(fmaxf(c0.x + b0v, c1.x + b1v), fmaxf(c2.x + b2v, c3.x + b3v)), 0.0f);
        r.w = fmaxf(fmaxf(fmaxf(c0.y + b0v, c1.y + b1v), fmaxf(c2.y + b2v, c3.y + b3v)), 0.0f);
        *(float4*)&g_h1[((og + o) * 196 + loc) * BATCH + b] = r;
    }
}

// ---------------------------------------------------------------------------
// conv2: untied 5x5, 6->16, +relu+pool. o-tile 2, thread = 4 images.
// Grid (25 loc, 8 og) = 200 CTAs x 256 thr.
// ---------------------------------------------------------------------------
__global__ __launch_bounds__(256) void k_conv2(const float* __restrict__ w2,
                                               const float* __restrict__ b2) {
    GDC_LAUNCH;
    __shared__ __align__(16) u64 ws[6][4][5][2][6];
    __shared__ float bs[2][4];
    int loc = blockIdx.x;
    int py = loc / 5, px = loc % 5;
    int og = blockIdx.y * 2;
    int tid = threadIdx.x;
    int b = tid * 4;

    for (int i = tid; i < 1200; i += 256) {
        int o = i / 600, r = i % 600;
        int pos = r / 150, r2 = r % 150;
        int c = r2 / 25, k = r2 % 25;
        int ky = k / 5, kx = k % 5;
        int ho = 2 * py + (pos >> 1), wo = 2 * px + (pos & 1);
        float w = w2[((((og + o) * 6 + c) * 10 + ho) * 10 + wo) * 25 + k];
        ws[c][pos][ky][o][kx] = pk2(w, w);
    }
    if (tid < 8) {
        int o = tid / 4, pos = tid % 4;
        int ho = 2 * py + (pos >> 1), wo = 2 * px + (pos & 1);
        bs[o][pos] = b2[((og + o) * 10 + ho) * 10 + wo];
    }
    __syncthreads();
    GDC_WAIT;   // g_h1 ready past here

    u64 acc[2][4][2];
#pragma unroll
    for (int i = 0; i < 16; i++) (&acc[0][0][0])[i] = 0ull;

    const float* base0 = &g_h1[((2 * py) * 14 + 2 * px) * BATCH + b];
    U2 abuf[2][6];
#pragma unroll
    for (int ix = 0; ix < 6; ix++) abuf[0][ix] = *(const U2*)&base0[ix * BATCH];

#pragma unroll 1
    for (int c = 0; c < 6; c++) {
        const float* base = base0 + c * (196 * BATCH);
#pragma unroll
        for (int iy = 0; iy < 6; iy++) {
            int cur = iy & 1, nxt = cur ^ 1;
            const float* np = (iy < 5) ? base + (iy + 1) * (14 * BATCH)
                                       : base + ((c < 5) ? 196 * BATCH : 0);
#pragma unroll
            for (int ix = 0; ix < 6; ix++) abuf[nxt][ix] = *(const U2*)&np[ix * BATCH];
#pragma unroll
            for (int dy = 0; dy < 2; dy++) {
                int ky = iy - dy;
                if (ky < 0 || ky > 4) continue;
#pragma unroll
                for (int o = 0; o < 2; o++)
#pragma unroll
                    for (int dx = 0; dx < 2; dx++) {
                        int pos = dy * 2 + dx;
                        U2 w01 = *(const U2*)&ws[c][pos][ky][o][0];
                        U2 w23 = *(const U2*)&ws[c][pos][ky][o][2];
                        u64 w4 = ws[c][pos][ky][o][4];
                        u64* ap = &acc[o][pos][0];
                        ap[0] = ffma2(w01.lo, abuf[cur][0 + dx].lo, ap[0]);
                        ap[1] = ffma2(w01.lo, abuf[cur][0 + dx].hi, ap[1]);
                        ap[0] = ffma2(w01.hi, abuf[cur][1 + dx].lo, ap[0]);
                        ap[1] = ffma2(w01.hi, abuf[cur][1 + dx].hi, ap[1]);
                        ap[0] = ffma2(w23.lo, abuf[cur][2 + dx].lo, ap[0]);
                        ap[1] = ffma2(w23.lo, abuf[cur][2 + dx].hi, ap[1]);
                        ap[0] = ffma2(w23.hi, abuf[cur][3 + dx].lo, ap[0]);
                        ap[1] = ffma2(w23.hi, abuf[cur][3 + dx].hi, ap[1]);
                        ap[0] = ffma2(w4, abuf[cur][4 + dx].lo, ap[0]);
                        ap[1] = ffma2(w4, abuf[cur][4 + dx].hi, ap[1]);
                    }
            }
        }
    }
#pragma unroll
    for (int o = 0; o < 2; o++) {
        float2 a0 = upk(acc[o][0][0]), a1 = upk(acc[o][1][0]);
        float2 a2 = upk(acc[o][2][0]), a3 = upk(acc[o][3][0]);
        float2 c0 = upk(acc[o][0][1]), c1 = upk(acc[o][1][1]);
        float2 c2 = upk(acc[o][2][1]), c3 = upk(acc[o][3][1]);
        float b0v = bs[o][0], b1v = bs[o][1], b2v = bs[o][2], b3v = bs[o][3];
        float4 r;
        r.x = fmaxf(fmaxf(fmaxf(a0.x + b0v, a1.x + b1v), fmaxf(a2.x + b2v, a3.x + b3v)), 0.0f);
        r.y = fmaxf(fmaxf(fmaxf(a0.y + b0v, a1.y + b1v), fmaxf(a2.y + b2v, a3.y + b3v)), 0.0f);
        r.z = fmaxf(fmaxf(fmaxf(c0.x + b0v, c1.x + b1v), fmaxf(c2.x + b2v, c3.x + b3v)), 0.0f);
        r.w = fmaxf(fmaxf(fmaxf(c0.y + b0v, c1.y + b1v), fmaxf(c2.y + b2v, c3.y + b3v)), 0.0f);
        *(float4*)&g_h2[((og + o) * 25 + loc) * BATCH + b] = r;
    }
}

// ---------------------------------------------------------------------------
// conv3: GEMM (120x1024x400). o-tile 8, K-split 20 (K=20), 256 thr, 4 img/thr.
// Grid (15, 20) = 300 CTAs.
// ---------------------------------------------------------------------------
__global__ __launch_bounds__(256) void k_conv3(const float* __restrict__ w3) {
    GDC_LAUNCH;
    __shared__ __align__(16) u64 ws[20][8];
    int og = blockIdx.x * 8;
    int k0 = blockIdx.y * 20;
    int tid = threadIdx.x;
    int b = tid * 4;

    if (tid < 160) {
        int o = tid & 7, k = tid >> 3;
        float w = w3[(og + o) * 400 + k0 + k];
        ws[k][o] = pk2(w, w);
    }
    __syncthreads();
    GDC_WAIT;   // g_h2 ready past here

    u64 acc[8][2];
#pragma unroll
    for (int i = 0; i < 16; i++) (&acc[0][0])[i] = 0ull;

    const float* hp = &g_h2[k0 * BATCH + b];
    U2 abuf[2][4];
#pragma unroll
    for (int j = 0; j < 4; j++) abuf[0][j] = *(const U2*)&hp[j * BATCH];

#pragma unroll 1
    for (int kk = 0; kk < 5; kk++) {
        int cur = kk & 1, nxt = cur ^ 1;
        const float* np = hp + ((kk < 4) ? (kk + 1) * (4 * BATCH) : 0);
#pragma unroll
        for (int j = 0; j < 4; j++) abuf[nxt][j] = *(const U2*)&np[j * BATCH];
#pragma unroll
        for (int j = 0; j < 4; j++)
#pragma unroll
            for (int op = 0; op < 4; op++) {
                U2 wp = *(const U2*)&ws[kk * 4 + j][2 * op];
                acc[2 * op][0]     = ffma2(wp.lo, abuf[cur][j].lo, acc[2 * op][0]);
                acc[2 * op][1]     = ffma2(wp.lo, abuf[cur][j].hi, acc[2 * op][1]);
                acc[2 * op + 1][0] = ffma2(wp.hi, abuf[cur][j].lo, acc[2 * op + 1][0]);
                acc[2 * op + 1][1] = ffma2(wp.hi, abuf[cur][j].hi, acc[2 * op + 1][1]);
            }
    }
#pragma unroll
    for (int o = 0; o < 8; o++) {
        U2 r; r.lo = acc[o][0]; r.hi = acc[o][1];
        *(U2*)&g_p3[(blockIdx.y * 120 + og + o) * BATCH + b] = r;
    }
}

// h3 = relu(sum_20 partials + bias)
__global__ __launch_bounds__(128) void k_h3fix(const float* __restrict__ b3) {
    GDC_LAUNCH;
    GDC_WAIT;   // g_p3 ready
    int i = blockIdx.x * 128 + threadIdx.x;   // float4 idx, 0..30719
    int o = i >> 8;
    float4 s = *(const float4*)&g_p3[i * 4];
#pragma unroll
    for (int p = 1; p < 20; p++) {
        float4 q = *(const float4*)&g_p3[p * 120 * BATCH + i * 4];
        s.x += q.x; s.y += q.y; s.z += q.z; s.w += q.w;
    }
    float bb = __ldg(&b3[o]);
    float4 r;
    r.x = fmaxf(s.x + bb, 0.0f);
    r.y = fmaxf(s.y + bb, 0.0f);
    r.z = fmaxf(s.z + bb, 0.0f);
    r.w = fmaxf(s.w + bb, 0.0f);
    *(float4*)&g_h3[i * 4] = r;
}

// ---------------------------------------------------------------------------
// fc2: GEMM (84x1024x120). o-tile 4, K-split 5 (K=24), 256 thr, 2 img/thr.
// Grid (21, 5, 2) = 210 CTAs.
// ---------------------------------------------------------------------------
__global__ __launch_bounds__(256) void k_fc2(const float* __restrict__ fw) {
    GDC_LAUNCH;
    __shared__ __align__(16) u64 ws[24][4];
    int og = blockIdx.x * 4;
    int k0 = blockIdx.y * 24;
    int tid = threadIdx.x;
    int b = (blockIdx.z * 256 + tid) * 2;

    if (tid < 96) {
        int o = tid & 3, k = tid >> 2;
        float w = fw[(og + o) * 120 + k0 + k];
        ws[k][o] = pk2(w, w);
    }
    __syncthreads();
    GDC_WAIT;   // g_h3 ready

    u64 acc[4];
#pragma unroll
    for (int o = 0; o < 4; o++) acc[o] = 0ull;

    const float* hp = &g_h3[k0 * BATCH + b];
    u64 abuf[2][8];
#pragma unroll
    for (int j = 0; j < 8; j++) abuf[0][j] = *(const u64*)&hp[j * BATCH];

#pragma unroll 1
    for (int kk = 0; kk < 3; kk++) {
        int cur = kk & 1, nxt = cur ^ 1;
        const float* np = hp + ((kk < 2) ? (kk + 1) * (8 * BATCH) : 0);
#pragma unroll
        for (int j = 0; j < 8; j++) abuf[nxt][j] = *(const u64*)&np[j * BATCH];
#pragma unroll
        for (int j = 0; j < 8; j++) {
            U2 w01 = *(const U2*)&ws[kk * 8 + j][0];
            U2 w23 = *(const U2*)&ws[kk * 8 + j][2];
            acc[0] = ffma2(w01.lo, abuf[cur][j], acc[0]);
            acc[1] = ffma2(w01.hi, abuf[cur][j], acc[1]);
            acc[2] = ffma2(w23.lo, abuf[cur][j], acc[2]);
            acc[3] = ffma2(w23.hi, abuf[cur][j], acc[3]);
        }
    }
#pragma unroll
    for (int o = 0; o < 4; o++)
        *(u64*)&g_p4[(blockIdx.y * 84 + og + o) * BATCH + b] = acc[o];
}

// h4 = relu(sum_5 partials + bias)
__global__ __launch_bounds__(128) void k_h4fix(const float* __restrict__ fb) {
    GDC_LAUNCH;
    GDC_WAIT;   // g_p4 ready
    int i = blockIdx.x * 128 + threadIdx.x;   // float4 idx, 0..21503
    int o = i >> 8;
    float4 s = *(const float4*)&g_p4[i * 4];
#pragma unroll
    for (int p = 1; p < 5; p++) {
        float4 q = *(const float4*)&g_p4[p * 84 * BATCH + i * 4];
        s.x += q.x; s.y += q.y; s.z += q.z; s.w += q.w;
    }
    float bb = __ldg(&fb[o]);
    float4 r;
    r.x = fmaxf(s.x + bb, 0.0f);
    r.y = fmaxf(s.y + bb, 0.0f);
    r.z = fmaxf(s.z + bb, 0.0f);
    r.w = fmaxf(s.w + bb, 0.0f);
    *(float4*)&g_h4[i * 4] = r;
}

// ---------------------------------------------------------------------------
// fc3: (10x1024x84) -> out (B,10). 32 CTAs x 160 thr (5 o-pairs x 32 img).
// ---------------------------------------------------------------------------
__global__ __launch_bounds__(160) void k_fc3(const float* __restrict__ fw,
                                             const float* __restrict__ fb,
                                             float* __restrict__ out) {
    GDC_LAUNCH;
    __shared__ u64 ws2[84][5];
    __shared__ float bsm[10];
    int tid = threadIdx.x;
    int p = tid >> 5;          // o-pair 0..4
    int img = tid & 31;
    int b = blockIdx.x * 32 + img;

    for (int i = tid; i < 420; i += 160) {
        int k = i / 5, q = i % 5;
        ws2[k][q] = pk2(fw[(2 * q) * 84 + k], fw[(2 * q + 1) * 84 + k]);
    }
    if (tid < 10) bsm[tid] = fb[tid];
    __syncthreads();
    GDC_WAIT;   // g_h4 ready

    u64 acc = 0ull;
#pragma unroll 1
    for (int k0 = 0; k0 < 84; k0 += 12) {
        float v[12];
#pragma unroll
        for (int j = 0; j < 12; j++) v[j] = g_h4[(k0 + j) * BATCH + b];
#pragma unroll
        for (int j = 0; j < 12; j++)
            acc = ffma2(ws2[k0 + j][p], pk2(v[j], v[j]), acc);
    }
    float2 r = upk(acc);
    out[b * 10 + 2 * p]     = r.x + bsm[2 * p];
    out[b * 10 + 2 * p + 1] = r.y + bsm[2 * p + 1];
}

// ---------------------------------------------------------------------------
// Host: launch with Programmatic Stream Serialization on all dependent
// kernels. Stream capture turns these into programmatic graph edges.
// ---------------------------------------------------------------------------
static inline void launch_pdl(const void* fn, dim3 g, dim3 b, void** args,
                              bool pdl) {
    cudaLaunchConfig_t cfg = {};
    cfg.gridDim = g;
    cfg.blockDim = b;
    cfg.dynamicSmemBytes = 0;
    cfg.stream = 0;
    cudaLaunchAttribute at;
    if (pdl) {
        at.id = cudaLaunchAttributeProgrammaticStreamSerialization;
        at.val.programmaticStreamSerializationAllowed = 1;
        cfg.attrs = &at;
        cfg.numAttrs = 1;
    }
    cudaLaunchKernelExC(&cfg, fn, args);
}

extern "C" void kernel_launch(void* const* d_in, const int* in_sizes, int n_in,
                              void* d_out, int out_size) {
    (void)in_sizes; (void)n_in; (void)out_size;
    const float* x     = (const float*)d_in[0];
    const float* w1    = (const float*)d_in[1];
    const float* b1    = (const float*)d_in[2];
    const float* w2    = (const float*)d_in[3];
    const float* b2    = (const float*)d_in[4];
    const float* w3    = (const float*)d_in[5];
    const float* b3    = (const float*)d_in[6];
    const float* fc2_w = (const float*)d_in[7];
    const float* fc2_b = (const float*)d_in[8];
    const float* fc3_w = (const float*)d_in[9];
    const float* fc3_b = (const float*)d_in[10];
    float* out = (float*)d_out;

    { void* a[] = { (void*)&x };
      launch_pdl((const void*)k_transpose, dim3(24, 32), dim3(256), a, false); }
    { void* a[] = { (void*)&w1, (void*)&b1 };
      launch_pdl((const void*)k_conv1, dim3(196, 2), dim3(256), a, true); }
    { void* a[] = { (void*)&w2, (void*)&b2 };
      launch_pdl((const void*)k_conv2, dim3(25, 8), dim3(256), a, true); }
    { void* a[] = { (void*)&w3 };
      launch_pdl((const void*)k_conv3, dim3(15, 20), dim3(256), a, true); }
    { void* a[] = { (void*)&b3 };
      launch_pdl((const void*)k_h3fix, dim3(240), dim3(128), a, true); }
    { void* a[] = { (void*)&fc2_w };
      launch_pdl((const void*)k_fc2, dim3(21, 5, 2), dim3(256), a, true); }
    { void* a[] = { (void*)&fc2_b };
      launch_pdl((const void*)k_h4fix, dim3(168), dim3(128), a, true); }
    { void* a[] = { (void*)&fc3_w, (void*)&fc3_b, (void*)&out };
      launch_pdl((const void*)k_fc3, dim3(32), dim3(160), a, true); }
}

// round 15
// speedup vs baseline: 1.1175x; 1.1175x over previous
#include <cuda_runtime.h>
#include <cuda_bf16.h>

#define BATCH 1024

#define GDC_LAUNCH asm volatile("griddepcontrol.launch_dependents;" ::: "memory")
#define GDC_WAIT   asm volatile("griddepcontrol.wait;" ::: "memory")

// ---------------------------------------------------------------------------
__device__ float g_xt[3 * 32 * 32 * BATCH];   // (3,32,32,B)
__device__ float g_h1[6 * 14 * 14 * BATCH];   // conv1+relu+pool
__device__ float g_h2[16 * 5 * 5 * BATCH];    // conv2+relu+pool
__device__ float g_p3[20 * 120 * BATCH];      // conv3 K-split partials (20 way)
__device__ float g_h3[120 * BATCH];           // conv3+relu
__device__ float g_p4[5 * 84 * BATCH];        // fc2 K-split partials (5 way)
__device__ float g_h4[84 * BATCH];            // fc2+relu

using u64 = unsigned long long;
struct __align__(16) U2 { u64 lo, hi; };

__device__ __forceinline__ u64 ffma2(u64 a, u64 b, u64 c) {
    u64 d;
    asm("fma.rn.f32x2 %0, %1, %2, %3;" : "=l"(d) : "l"(a), "l"(b), "l"(c));
    return d;
}
__device__ __forceinline__ u64 pk2(float x, float y) {
    u64 r; asm("mov.b64 %0, {%1, %2};" : "=l"(r) : "f"(x), "f"(y)); return r;
}
__device__ __forceinline__ float2 upk(u64 v) {
    float2 r; asm("mov.b64 {%0, %1}, %2;" : "=f"(r.x), "=f"(r.y) : "l"(v)); return r;
}

// ---------------------------------------------------------------------------
// Transpose x (B,3072) -> (3072,B)
// ---------------------------------------------------------------------------
__global__ __launch_bounds__(256) void k_transpose(const float* __restrict__ x) {
    GDC_LAUNCH;
    __shared__ float t[32][133];
    int p0 = blockIdx.x * 128;
    int b0 = blockIdx.y * 32;
    int tx = threadIdx.x & 31, ty = threadIdx.x >> 5;
#pragma unroll
    for (int rr = 0; rr < 4; rr++) {
        int row = ty + 8 * rr;
        float4 v = *(const float4*)&x[(b0 + row) * 3072 + p0 + 4 * tx];
        t[row][4 * tx + 0] = v.x; t[row][4 * tx + 1] = v.y;
        t[row][4 * tx + 2] = v.z; t[row][4 * tx + 3] = v.w;
    }
    __syncthreads();
#pragma unroll
    for (int q = 0; q < 4; q++) {
        int idx = q * 256 + threadIdx.x;
        int pp = idx >> 3;
        int bg = idx & 7;
        float4 v = make_float4(t[4 * bg + 0][pp], t[4 * bg + 1][pp],
                               t[4 * bg + 2][pp], t[4 * bg + 3][pp]);
        *(float4*)&g_xt[(p0 + pp) * BATCH + b0 + 4 * bg] = v;
    }
}

// ---------------------------------------------------------------------------
// conv1: untied 5x5, 3->6, +relu+pool. o-tile 3, thread = 4 images.
// Grid (196 loc, 2 og) = 392 CTAs x 256 thr.
// ---------------------------------------------------------------------------
__global__ __launch_bounds__(256) void k_conv1(const float* __restrict__ w1,
                                               const float* __restrict__ b1) {
    GDC_LAUNCH;
    __shared__ __align__(16) u64 ws[3][4][5][3][6];   // [c][pos][ky][o][kx]
    __shared__ float bs[3][4];
    int loc = blockIdx.x;
    int py = loc / 14, px = loc % 14;
    int og = blockIdx.y * 3;
    int tid = threadIdx.x;
    int b = tid * 4;

    for (int i = tid; i < 900; i += 256) {
        int o = i / 300, r = i % 300;
        int pos = r / 75, r2 = r % 75;
        int c = r2 / 25, k = r2 % 25;
        int ky = k / 5, kx = k % 5;
        int ho = 2 * py + (pos >> 1), wo = 2 * px + (pos & 1);
        float w = w1[((((og + o) * 3 + c) * 28 + ho) * 28 + wo) * 25 + k];
        ws[c][pos][ky][o][kx] = pk2(w, w);
    }
    if (tid < 12) {
        int o = tid / 4, pos = tid % 4;
        int ho = 2 * py + (pos >> 1), wo = 2 * px + (pos & 1);
        bs[o][pos] = b1[((og + o) * 28 + ho) * 28 + wo];
    }
    __syncthreads();
    GDC_WAIT;   // g_xt ready past here

    u64 acc[3][4][2];
#pragma unroll
    for (int i = 0; i < 24; i++) (&acc[0][0][0])[i] = 0ull;

    const float* base0 = &g_xt[((2 * py) * 32 + 2 * px) * BATCH + b];
    U2 abuf[2][6];
#pragma unroll
    for (int ix = 0; ix < 6; ix++) abuf[0][ix] = *(const U2*)&base0[ix * BATCH];

#pragma unroll 1
    for (int c = 0; c < 3; c++) {
        const float* base = base0 + c * (1024 * BATCH);
#pragma unroll
        for (int iy = 0; iy < 6; iy++) {
            int cur = iy & 1, nxt = cur ^ 1;
            const float* np = (iy < 5) ? base + (iy + 1) * (32 * BATCH)
                                       : base + ((c < 2) ? 1024 * BATCH : 0);
#pragma unroll
            for (int ix = 0; ix < 6; ix++) abuf[nxt][ix] = *(const U2*)&np[ix * BATCH];
#pragma unroll
            for (int dy = 0; dy < 2; dy++) {
                int ky = iy - dy;
                if (ky < 0 || ky > 4) continue;
#pragma unroll
                for (int o = 0; o < 3; o++)
#pragma unroll
                    for (int dx = 0; dx < 2; dx++) {
                        int pos = dy * 2 + dx;
                        U2 w01 = *(const U2*)&ws[c][pos][ky][o][0];
                        U2 w23 = *(const U2*)&ws[c][pos][ky][o][2];
                        u64 w4 = ws[c][pos][ky][o][4];
                        u64* ap = &acc[o][pos][0];
                        ap[0] = ffma2(w01.lo, abuf[cur][0 + dx].lo, ap[0]);
                        ap[1] = ffma2(w01.lo, abuf[cur][0 + dx].hi, ap[1]);
                        ap[0] = ffma2(w01.hi, abuf[cur][1 + dx].lo, ap[0]);
                        ap[1] = ffma2(w01.hi, abuf[cur][1 + dx].hi, ap[1]);
                        ap[0] = ffma2(w23.lo, abuf[cur][2 + dx].lo, ap[0]);
                        ap[1] = ffma2(w23.lo, abuf[cur][2 + dx].hi, ap[1]);
                        ap[0] = ffma2(w23.hi, abuf[cur][3 + dx].lo, ap[0]);
                        ap[1] = ffma2(w23.hi, abuf[cur][3 + dx].hi, ap[1]);
                        ap[0] = ffma2(w4, abuf[cur][4 + dx].lo, ap[0]);
                        ap[1] = ffma2(w4, abuf[cur][4 + dx].hi, ap[1]);
                    }
            }
        }
    }
#pragma unroll
    for (int o = 0; o < 3; o++) {
        float2 a0 = upk(acc[o][0][0]), a1 = upk(acc[o][1][0]);
        float2 a2 = upk(acc[o][2][0]), a3 = upk(acc[o][3][0]);
        float2 c0 = upk(acc[o][0][1]), c1 = upk(acc[o][1][1]);
        float2 c2 = upk(acc[o][2][1]), c3 = upk(acc[o][3][1]);
        float b0v = bs[o][0], b1v = bs[o][1], b2v = bs[o][2], b3v = bs[o][3];
        float4 r;
        r.x = fmaxf(fmaxf(fmaxf(a0.x + b0v, a1.x + b1v), fmaxf(a2.x + b2v, a3.x + b3v)), 0.0f);
        r.y = fmaxf(fmaxf(fmaxf(a0.y + b0v, a1.y + b1v), fmaxf(a2.y + b2v, a3.y + b3v)), 0.0f);
        r.z = fmaxf(fmaxf(fmaxf(c0.x + b0v, c1.x + b1v), fmaxf(c2.x + b2v, c3.x + b3v)), 0.0f);
        r.w = fmaxf(fmaxf(fmaxf(c0.y + b0v, c1.y + b1v), fmaxf(c2.y + b2v, c3.y + b3v)), 0.0f);
        *(float4*)&g_h1[((og + o) * 196 + loc) * BATCH + b] = r;
    }
}

// ---------------------------------------------------------------------------
// conv2: untied 5x5, 6->16, +relu+pool. o-tile 2, thread = 4 images.
// Grid (25 loc, 8 og) = 200 CTAs x 256 thr.
// ---------------------------------------------------------------------------
__global__ __launch_bounds__(256) void k_conv2(const float* __restrict__ w2,
                                               const float* __restrict__ b2) {
    GDC_LAUNCH;
    __shared__ __align__(16) u64 ws[6][4][5][2][6];
    __shared__ float bs[2][4];
    int loc = blockIdx.x;
    int py = loc / 5, px = loc % 5;
    int og = blockIdx.y * 2;
    int tid = threadIdx.x;
    int b = tid * 4;

    for (int i = tid; i < 1200; i += 256) {
        int o = i / 600, r = i % 600;
        int pos = r / 150, r2 = r % 150;
        int c = r2 / 25, k = r2 % 25;
        int ky = k / 5, kx = k % 5;
        int ho = 2 * py + (pos >> 1), wo = 2 * px + (pos & 1);
        float w = w2[((((og + o) * 6 + c) * 10 + ho) * 10 + wo) * 25 + k];
        ws[c][pos][ky][o][kx] = pk2(w, w);
    }
    if (tid < 8) {
        int o = tid / 4, pos = tid % 4;
        int ho = 2 * py + (pos >> 1), wo = 2 * px + (pos & 1);
        bs[o][pos] = b2[((og + o) * 10 + ho) * 10 + wo];
    }
    __syncthreads();
    GDC_WAIT;   // g_h1 ready past here

    u64 acc[2][4][2];
#pragma unroll
    for (int i = 0; i < 16; i++) (&acc[0][0][0])[i] = 0ull;

    const float* base0 = &g_h1[((2 * py) * 14 + 2 * px) * BATCH + b];
    U2 abuf[2][6];
#pragma unroll
    for (int ix = 0; ix < 6; ix++) abuf[0][ix] = *(const U2*)&base0[ix * BATCH];

#pragma unroll 1
    for (int c = 0; c < 6; c++) {
        const float* base = base0 + c * (196 * BATCH);
#pragma unroll
        for (int iy = 0; iy < 6; iy++) {
            int cur = iy & 1, nxt = cur ^ 1;
            const float* np = (iy < 5) ? base + (iy + 1) * (14 * BATCH)
                                       : base + ((c < 5) ? 196 * BATCH : 0);
#pragma unroll
            for (int ix = 0; ix < 6; ix++) abuf[nxt][ix] = *(const U2*)&np[ix * BATCH];
#pragma unroll
            for (int dy = 0; dy < 2; dy++) {
                int ky = iy - dy;
                if (ky < 0 || ky > 4) continue;
#pragma unroll
                for (int o = 0; o < 2; o++)
#pragma unroll
                    for (int dx = 0; dx < 2; dx++) {
                        int pos = dy * 2 + dx;
                        U2 w01 = *(const U2*)&ws[c][pos][ky][o][0];
                        U2 w23 = *(const U2*)&ws[c][pos][ky][o][2];
                        u64 w4 = ws[c][pos][ky][o][4];
                        u64* ap = &acc[o][pos][0];
                        ap[0] = ffma2(w01.lo, abuf[cur][0 + dx].lo, ap[0]);
                        ap[1] = ffma2(w01.lo, abuf[cur][0 + dx].hi, ap[1]);
                        ap[0] = ffma2(w01.hi, abuf[cur][1 + dx].lo, ap[0]);
                        ap[1] = ffma2(w01.hi, abuf[cur][1 + dx].hi, ap[1]);
                        ap[0] = ffma2(w23.lo, abuf[cur][2 + dx].lo, ap[0]);
                        ap[1] = ffma2(w23.lo, abuf[cur][2 + dx].hi, ap[1]);
                        ap[0] = ffma2(w23.hi, abuf[cur][3 + dx].lo, ap[0]);
                        ap[1] = ffma2(w23.hi, abuf[cur][3 + dx].hi, ap[1]);
                        ap[0] = ffma2(w4, abuf[cur][4 + dx].lo, ap[0]);
                        ap[1] = ffma2(w4, abuf[cur][4 + dx].hi, ap[1]);
                    }
            }
        }
    }
#pragma unroll
    for (int o = 0; o < 2; o++) {
        float2 a0 = upk(acc[o][0][0]), a1 = upk(acc[o][1][0]);
        float2 a2 = upk(acc[o][2][0]), a3 = upk(acc[o][3][0]);
        float2 c0 = upk(acc[o][0][1]), c1 = upk(acc[o][1][1]);
        float2 c2 = upk(acc[o][2][1]), c3 = upk(acc[o][3][1]);
        float b0v = bs[o][0], b1v = bs[o][1], b2v = bs[o][2], b3v = bs[o][3];
        float4 r;
        r.x = fmaxf(fmaxf(fmaxf(a0.x + b0v, a1.x + b1v), fmaxf(a2.x + b2v, a3.x + b3v)), 0.0f);
        r.y = fmaxf(fmaxf(fmaxf(a0.y + b0v, a1.y + b1v), fmaxf(a2.y + b2v, a3.y + b3v)), 0.0f);
        r.z = fmaxf(fmaxf(fmaxf(c0.x + b0v, c1.x + b1v), fmaxf(c2.x + b2v, c3.x + b3v)), 0.0f);
        r.w = fmaxf(fmaxf(fmaxf(c0.y + b0v, c1.y + b1v), fmaxf(c2.y + b2v, c3.y + b3v)), 0.0f);
        *(float4*)&g_h2[((og + o) * 25 + loc) * BATCH + b] = r;
    }
}

// ---------------------------------------------------------------------------
// conv3 SMEM-STAGED: each CTA stages its (20 K x 1024 B) activation slice
// (80 KB dynamic smem) with 20 independent float4 loads/thread, then runs the
// GEMM mainloop entirely from smem. o-tile 8, grid (15, 20) = 300 CTAs,
// 256 thr, 4 img/thread.
// ---------------------------------------------------------------------------
__global__ __launch_bounds__(256) void k_conv3(const float* __restrict__ w3) {
    GDC_LAUNCH;
    extern __shared__ float sh[];                 // 20 * 1024 floats = 80 KB
    __shared__ __align__(16) u64 ws[20][8];
    int og = blockIdx.x * 8;
    int k0 = blockIdx.y * 20;
    int tid = threadIdx.x;
    int b = tid * 4;

    if (tid < 160) {
        int o = tid & 7, k = tid >> 3;
        float w = w3[(og + o) * 400 + k0 + k];
        ws[k][o] = pk2(w, w);
    }
    GDC_WAIT;   // g_h2 ready past here

    // Cooperative stage: 5120 float4, 20 per thread, all independent (MLP~20).
    {
        const float4* src = (const float4*)&g_h2[k0 * BATCH];
        float4* dst = (float4*)sh;
#pragma unroll
        for (int q = 0; q < 20; q++)
            dst[q * 256 + tid] = src[q * 256 + tid];
    }
    __syncthreads();

    u64 acc[8][2];
#pragma unroll
    for (int i = 0; i < 16; i++) (&acc[0][0])[i] = 0ull;

#pragma unroll 4
    for (int k = 0; k < 20; k++) {
        U2 a = *(const U2*)&sh[k * 1024 + b];
#pragma unroll
        for (int op = 0; op < 4; op++) {
            U2 wp = *(const U2*)&ws[k][2 * op];
            acc[2 * op][0]     = ffma2(wp.lo, a.lo, acc[2 * op][0]);
            acc[2 * op][1]     = ffma2(wp.lo, a.hi, acc[2 * op][1]);
            acc[2 * op + 1][0] = ffma2(wp.hi, a.lo, acc[2 * op + 1][0]);
            acc[2 * op + 1][1] = ffma2(wp.hi, a.hi, acc[2 * op + 1][1]);
        }
    }
#pragma unroll
    for (int o = 0; o < 8; o++) {
        U2 r; r.lo = acc[o][0]; r.hi = acc[o][1];
        *(U2*)&g_p3[(blockIdx.y * 120 + og + o) * BATCH + b] = r;
    }
}

// h3 = relu(sum_20 partials + bias)
__global__ __launch_bounds__(128) void k_h3fix(const float* __restrict__ b3) {
    GDC_LAUNCH;
    GDC_WAIT;   // g_p3 ready
    int i = blockIdx.x * 128 + threadIdx.x;   // float4 idx, 0..30719
    int o = i >> 8;
    float4 s = *(const float4*)&g_p3[i * 4];
#pragma unroll
    for (int p = 1; p < 20; p++) {
        float4 q = *(const float4*)&g_p3[p * 120 * BATCH + i * 4];
        s.x += q.x; s.y += q.y; s.z += q.z; s.w += q.w;
    }
    float bb = __ldg(&b3[o]);
    float4 r;
    r.x = fmaxf(s.x + bb, 0.0f);
    r.y = fmaxf(s.y + bb, 0.0f);
    r.z = fmaxf(s.z + bb, 0.0f);
    r.w = fmaxf(s.w + bb, 0.0f);
    *(float4*)&g_h3[i * 4] = r;
}

// ---------------------------------------------------------------------------
// fc2: GEMM (84x1024x120). o-tile 4, K-split 5 (K=24), 256 thr, 2 img/thr.
// Grid (21, 5, 2) = 210 CTAs.
// ---------------------------------------------------------------------------
__global__ __launch_bounds__(256) void k_fc2(const float* __restrict__ fw) {
    GDC_LAUNCH;
    __shared__ __align__(16) u64 ws[24][4];
    int og = blockIdx.x * 4;
    int k0 = blockIdx.y * 24;
    int tid = threadIdx.x;
    int b = (blockIdx.z * 256 + tid) * 2;

    if (tid < 96) {
        int o = tid & 3, k = tid >> 2;
        float w = fw[(og + o) * 120 + k0 + k];
        ws[k][o] = pk2(w, w);
    }
    __syncthreads();
    GDC_WAIT;   // g_h3 ready

    u64 acc[4];
#pragma unroll
    for (int o = 0; o < 4; o++) acc[o] = 0ull;

    const float* hp = &g_h3[k0 * BATCH + b];
    u64 abuf[2][8];
#pragma unroll
    for (int j = 0; j < 8; j++) abuf[0][j] = *(const u64*)&hp[j * BATCH];

#pragma unroll 1
    for (int kk = 0; kk < 3; kk++) {
        int cur = kk & 1, nxt = cur ^ 1;
        const float* np = hp + ((kk < 2) ? (kk + 1) * (8 * BATCH) : 0);
#pragma unroll
        for (int j = 0; j < 8; j++) abuf[nxt][j] = *(const u64*)&np[j * BATCH];
#pragma unroll
        for (int j = 0; j < 8; j++) {
            U2 w01 = *(const U2*)&ws[kk * 8 + j][0];
            U2 w23 = *(const U2*)&ws[kk * 8 + j][2];
            acc[0] = ffma2(w01.lo, abuf[cur][j], acc[0]);
            acc[1] = ffma2(w01.hi, abuf[cur][j], acc[1]);
            acc[2] = ffma2(w23.lo, abuf[cur][j], acc[2]);
            acc[3] = ffma2(w23.hi, abuf[cur][j], acc[3]);
        }
    }
#pragma unroll
    for (int o = 0; o < 4; o++)
        *(u64*)&g_p4[(blockIdx.y * 84 + og + o) * BATCH + b] = acc[o];
}

// h4 = relu(sum_5 partials + bias)
__global__ __launch_bounds__(128) void k_h4fix(const float* __restrict__ fb) {
    GDC_LAUNCH;
    GDC_WAIT;   // g_p4 ready
    int i = blockIdx.x * 128 + threadIdx.x;   // float4 idx, 0..21503
    int o = i >> 8;
    float4 s = *(const float4*)&g_p4[i * 4];
#pragma unroll
    for (int p = 1; p < 5; p++) {
        float4 q = *(const float4*)&g_p4[p * 84 * BATCH + i * 4];
        s.x += q.x; s.y += q.y; s.z += q.z; s.w += q.w;
    }
    float bb = __ldg(&fb[o]);
    float4 r;
    r.x = fmaxf(s.x + bb, 0.0f);
    r.y = fmaxf(s.y + bb, 0.0f);
    r.z = fmaxf(s.z + bb, 0.0f);
    r.w = fmaxf(s.w + bb, 0.0f);
    *(float4*)&g_h4[i * 4] = r;
}

// ---------------------------------------------------------------------------
// fc3: (10x1024x84) -> out (B,10). 32 CTAs x 160 thr (5 o-pairs x 32 img).
// ---------------------------------------------------------------------------
__global__ __launch_bounds__(160) void k_fc3(const float* __restrict__ fw,
                                             const float* __restrict__ fb,
                                             float* __restrict__ out) {
    GDC_LAUNCH;
    __shared__ u64 ws2[84][5];
    __shared__ float bsm[10];
    int tid = threadIdx.x;
    int p = tid >> 5;          // o-pair 0..4
    int img = tid & 31;
    int b = blockIdx.x * 32 + img;

    for (int i = tid; i < 420; i += 160) {
        int k = i / 5, q = i % 5;
        ws2[k][q] = pk2(fw[(2 * q) * 84 + k], fw[(2 * q + 1) * 84 + k]);
    }
    if (tid < 10) bsm[tid] = fb[tid];
    __syncthreads();
    GDC_WAIT;   // g_h4 ready

    u64 acc = 0ull;
#pragma unroll 1
    for (int k0 = 0; k0 < 84; k0 += 12) {
        float v[12];
#pragma unroll
        for (int j = 0; j < 12; j++) v[j] = g_h4[(k0 + j) * BATCH + b];
#pragma unroll
        for (int j = 0; j < 12; j++)
            acc = ffma2(ws2[k0 + j][p], pk2(v[j], v[j]), acc);
    }
    float2 r = upk(acc);
    out[b * 10 + 2 * p]     = r.x + bsm[2 * p];
    out[b * 10 + 2 * p + 1] = r.y + bsm[2 * p + 1];
}

// ---------------------------------------------------------------------------
static inline void launch_pdl(const void* fn, dim3 g, dim3 b, void** args,
                              bool pdl, size_t smem = 0) {
    cudaLaunchConfig_t cfg = {};
    cfg.gridDim = g;
    cfg.blockDim = b;
    cfg.dynamicSmemBytes = smem;
    cfg.stream = 0;
    cudaLaunchAttribute at;
    if (pdl) {
        at.id = cudaLaunchAttributeProgrammaticStreamSerialization;
        at.val.programmaticStreamSerializationAllowed = 1;
        cfg.attrs = &at;
        cfg.numAttrs = 1;
    }
    cudaLaunchKernelExC(&cfg, fn, args);
}

extern "C" void kernel_launch(void* const* d_in, const int* in_sizes, int n_in,
                              void* d_out, int out_size) {
    (void)in_sizes; (void)n_in; (void)out_size;
    const float* x     = (const float*)d_in[0];
    const float* w1    = (const float*)d_in[1];
    const float* b1    = (const float*)d_in[2];
    const float* w2    = (const float*)d_in[3];
    const float* b2    = (const float*)d_in[4];
    const float* w3    = (const float*)d_in[5];
    const float* b3    = (const float*)d_in[6];
    const float* fc2_w = (const float*)d_in[7];
    const float* fc2_b = (const float*)d_in[8];
    const float* fc3_w = (const float*)d_in[9];
    const float* fc3_b = (const float*)d_in[10];
    float* out = (float*)d_out;

    const size_t CONV3_SMEM = 20 * 1024 * sizeof(float);   // 80 KB
    cudaFuncSetAttribute((const void*)k_conv3,
                         cudaFuncAttributeMaxDynamicSharedMemorySize,
                         (int)CONV3_SMEM);

    { void* a[] = { (void*)&x };
      launch_pdl((const void*)k_transpose, dim3(24, 32), dim3(256), a, false); }
    { void* a[] = { (void*)&w1, (void*)&b1 };
      launch_pdl((const void*)k_conv1, dim3(196, 2), dim3(256), a, true); }
    { void* a[] = { (void*)&w2, (void*)&b2 };
      launch_pdl((const void*)k_conv2, dim3(25, 8), dim3(256), a, true); }
    { void* a[] = { (void*)&w3 };
      launch_pdl((const void*)k_conv3, dim3(15, 20), dim3(256), a, true, CONV3_SMEM); }
    { void* a[] = { (void*)&b3 };
      launch_pdl((const void*)k_h3fix, dim3(240), dim3(128), a, true); }
    { void* a[] = { (void*)&fc2_w };
      launch_pdl((const void*)k_fc2, dim3(21, 5, 2), dim3(256), a, true); }
    { void* a[] = { (void*)&fc2_b };
      launch_pdl((const void*)k_h4fix, dim3(168), dim3(128), a, true); }
    { void* a[] = { (void*)&fc3_w, (void*)&fc3_b, (void*)&out };
      launch_pdl((const void*)k_fc3, dim3(32), dim3(160), a, true); }
}